// round 14
// baseline (speedup 1.0000x reference)
#include <cuda_runtime.h>
#include <cuda_fp16.h>
#include <math.h>
#include <stdint.h>

// Problem constants
#define BB 32
#define TT 2048
#define HH 1024
#define UU 1024
#define KN 32
#define KSZ 15
#define KW 31
#define KAUG (HH + KN)   // 1056
#define KP 1056          // K (33 * 32 exactly)
#define BK 32            // K per chunk (fp16) = 64 bytes per row
#define NCHUNK (KP / BK) // 33
#define NSTAGE 6

#define BM 128
#define BN 128

// Output layout in d_out (float):
#define OUT_CTX 0
#define OUT_ATT (BB * HH)
#define OUT_SCORE (BB * HH + BB * TT)

// prep kernel block-range dispatch
#define NB_A (BB * TT)           // 65536 convertA blocks
#define NB_DB (UU / 8)           // 128 dbias blocks
#define NB_W UU                  // 1024 convertW blocks
#define NB_INIT 256              // init blocks
#define NB_PREP (NB_A + NB_DB + NB_W + NB_INIT)

// Scratch (device globals)
__device__ float g_dbias[BB * UU];
__device__ __half g_Ah[(size_t)BB * TT * KP];   // fp16(values | loc)
__device__ __half g_Wh[(size_t)UU * KP];        // fp16(W1_w | loc_proj_w)

// ---------------------------------------------------------------------------
__device__ __forceinline__ uint32_t smem_u32(const void* p) {
    uint32_t a;
    asm("{ .reg .u64 t; cvta.to.shared.u64 t, %1; cvt.u32.u64 %0, t; }"
        : "=r"(a) : "l"(p));
    return a;
}

__device__ __forceinline__ void cp16(uint32_t saddr, const void* gaddr) {
    asm volatile("cp.async.cg.shared.global [%0], [%1], 16;"
                 :: "r"(saddr), "l"(gaddr));
}
#define CP_COMMIT() asm volatile("cp.async.commit_group;" ::: "memory")
#define CP_WAIT5()  asm volatile("cp.async.wait_group 5;" ::: "memory")

__device__ __forceinline__ void ldm_x4(uint32_t* r, uint32_t addr) {
    asm volatile("ldmatrix.sync.aligned.m8n8.x4.shared.b16 {%0,%1,%2,%3}, [%4];"
                 : "=r"(r[0]), "=r"(r[1]), "=r"(r[2]), "=r"(r[3]) : "r"(addr));
}

__device__ __forceinline__ void mma16816(float* d, const uint32_t* a,
                                         uint32_t b0, uint32_t b1) {
    asm volatile(
        "mma.sync.aligned.m16n8k16.row.col.f32.f16.f16.f32 "
        "{%0,%1,%2,%3}, {%4,%5,%6,%7}, {%8,%9}, {%0,%1,%2,%3};"
        : "+f"(d[0]), "+f"(d[1]), "+f"(d[2]), "+f"(d[3])
        : "r"(a[0]), "r"(a[1]), "r"(a[2]), "r"(a[3]), "r"(b0), "r"(b1));
}

__device__ __forceinline__ float tanh_fast(float x) {
    float y;
    asm("tanh.approx.f32 %0, %1;" : "=f"(y) : "f"(x));
    return y;
}

// swizzle: 64B rows, XOR bits[5:4] with row bits[2:1] -> conflict-free ldmatrix
__device__ __forceinline__ uint32_t swz(int row, int inrow) {
    return (uint32_t)(row * 64 + (inrow ^ ((row & 6) << 3)));
}

// ---------------------------------------------------------------------------
// 1) Mega prep kernel: convertA (conv fused) | dbias | convertW | init_out
//    dispatched by blockIdx.x range; all parts independent.
// ---------------------------------------------------------------------------
__global__ void __launch_bounds__(256)
prep_kernel(const float* __restrict__ values,
            const float* __restrict__ prev,
            const float* __restrict__ convw,
            const float* __restrict__ q,
            const float* __restrict__ W2w,
            const float* __restrict__ W1b,
            const float* __restrict__ W2b,
            const float* __restrict__ W1w,
            const float* __restrict__ locpw,
            const float* __restrict__ Vb,
            float* __restrict__ out) {
    int bid = (int)blockIdx.x;
    int tid = (int)threadIdx.x;

    if (bid < NB_A) {
        // ---- convertA: row (b,t) -> g_Ah[row] = fp16(values[row] | loc) ----
        int row = bid;
        int b = row >> 11;                // TT = 2048
        int t = row & (TT - 1);
        __shared__ float loc[KN];

        if (tid < KN) {
            const float* pb = prev + b * TT;
            const float* w = convw + tid * KW;
            float acc = 0.f;
#pragma unroll
            for (int j = 0; j < KW; j++) {
                int tt = t + j - KSZ;
                float p = (tt >= 0 && tt < TT) ? pb[tt] : 0.f;
                acc = fmaf(p, w[j], acc);
            }
            loc[tid] = acc;
        }

        const float4* vrow = (const float4*)(values + (size_t)row * HH);
        __half* ah = g_Ah + (size_t)row * KP;
        {
            float4 v = vrow[tid];
            __half2* o = (__half2*)(ah + tid * 4);
            o[0] = __floats2half2_rn(v.x, v.y);
            o[1] = __floats2half2_rn(v.z, v.w);
        }
        __syncthreads();
        if (tid < 8) {
            const float4* lrow = (const float4*)loc;
            float4 v = lrow[tid];
            __half2* o = (__half2*)(ah + HH + tid * 4);
            o[0] = __floats2half2_rn(v.x, v.y);
            o[1] = __floats2half2_rn(v.z, v.w);
        }
    } else if (bid < NB_A + NB_DB) {
        // ---- dbias: d[b][u] = W1_b[u] + W2_b[u] + q[b].W2_w[u] ----
        int bi = bid - NB_A;
        int warp = tid >> 5;
        int lane = tid & 31;
        int u = bi * 8 + warp;
        float w2[32];
#pragma unroll
        for (int i = 0; i < 32; i++) w2[i] = W2w[(size_t)u * HH + lane + 32 * i];
        float bias = W1b[u] + W2b[u];
        for (int b = 0; b < BB; b++) {
            float p = 0.f;
            const float* qb = q + (size_t)b * HH;
#pragma unroll
            for (int i = 0; i < 32; i++) p = fmaf(w2[i], qb[lane + 32 * i], p);
#pragma unroll
            for (int off = 16; off; off >>= 1) p += __shfl_xor_sync(0xFFFFFFFFu, p, off);
            if (lane == 0) g_dbias[b * UU + u] = p + bias;
        }
    } else if (bid < NB_A + NB_DB + NB_W) {
        // ---- convertW: [W1_w | loc_proj_w] -> fp16 ----
        size_t u = bid - (NB_A + NB_DB);
        const float* w1 = W1w + u * HH;
        const float* lp = locpw + u * KN;
        __half* wh = g_Wh + u * KP;
        for (int k = tid; k < KP; k += 256) {
            float a = (k < HH) ? w1[k] : lp[k - HH];
            wh[k] = __float2half_rn(a);
        }
    } else {
        // ---- init_out: score = V_b, context = 0 ----
        int bi = bid - (NB_A + NB_DB + NB_W);
        int stride = NB_INIT * 256;
        int tid0 = bi * 256 + tid;
        float vb = Vb[0];
        for (int i = tid0; i < BB * TT; i += stride) out[OUT_SCORE + i] = vb;
        for (int i = tid0; i < BB * HH; i += stride) out[OUT_CTX + i] = 0.f;
    }
}

// ---------------------------------------------------------------------------
// 2) HMMA fp16 score GEMM, fused tanh + V_w epilogue
//    CTA 128x128, 8 warps (4m x 2n), BK=32, 6-stage cp.async (R8 loop order)
// ---------------------------------------------------------------------------
#define STG_A 0
#define STG_B 8192
#define STG_SZ 16384
#define SM_RED (NSTAGE * STG_SZ)                 // 98304
#define SMEM_GEMM_BYTES (NSTAGE * STG_SZ + BM * 8 * 4)   // 102400

__global__ void __launch_bounds__(256, 2)
score_gemm_tc(const float* __restrict__ Vw, float* __restrict__ out) {
    extern __shared__ char smem[];
    uint32_t sb = smem_u32(smem);

    int tid = (int)threadIdx.x;
    int lane = tid & 31;
    int wid = tid >> 5;
    int warp_m = wid >> 1;   // 0..3
    int warp_n = wid & 1;    // 0..1
    int b = blockIdx.z;
    int tTile = blockIdx.x;
    int uTile = blockIdx.y;

    size_t aRow0 = (size_t)b * TT + tTile * BM;
    size_t uRow0 = (size_t)uTile * BN;

    // per-thread load slots: 2 x 16B per array per chunk
    uint32_t swoff[2];
    size_t gbA[2], gbB[2];
#pragma unroll
    for (int r = 0; r < 2; r++) {
        int id = tid * 2 + r;
        int row = id >> 2;
        int sl = id & 3;
        swoff[r] = swz(row, sl * 16);
        gbA[r] = ((aRow0 + row) * KP + sl * 8) * 2;   // bytes
        gbB[r] = ((uRow0 + row) * KP + sl * 8) * 2;
    }

    const char* pA = (const char*)g_Ah;
    const char* pW = (const char*)g_Wh;

    // prologue: stages 0..5
#pragma unroll
    for (int c = 0; c < NSTAGE; c++) {
        uint32_t s0 = sb + c * STG_SZ;
        size_t gk = (size_t)c * BK * 2;
#pragma unroll
        for (int r = 0; r < 2; r++) {
            cp16(s0 + STG_A + swoff[r], pA + gbA[r] + gk);
            cp16(s0 + STG_B + swoff[r], pW + gbB[r] + gk);
        }
        CP_COMMIT();
    }

    float acc[2][8][4];
#pragma unroll
    for (int mt = 0; mt < 2; mt++)
#pragma unroll
        for (int nt = 0; nt < 8; nt++)
#pragma unroll
            for (int i = 0; i < 4; i++) acc[mt][nt][i] = 0.f;

    int slot = 0;
    for (int c = 0; c < NCHUNK; c++) {
        CP_WAIT5();
        __syncthreads();
        uint32_t s0 = sb + slot * STG_SZ;

#pragma unroll
        for (int ks = 0; ks < 2; ks++) {
            uint32_t ah[8];
#pragma unroll
            for (int mt = 0; mt < 2; mt++) {
                int row = warp_m * 32 + mt * 16 + (lane & 15);
                uint32_t off = swz(row, (ks * 2 + (lane >> 4)) * 16);
                ldm_x4(ah + mt * 4, s0 + STG_A + off);
            }
            uint32_t bb[16];
#pragma unroll
            for (int p = 0; p < 4; p++) {
                int t = lane >> 3;
                int n = warp_n * 64 + p * 16 + ((t & 2) ? 8 : 0) + (lane & 7);
                int koff = ks * 32 + ((t & 1) ? 16 : 0);
                ldm_x4(bb + p * 4, s0 + STG_B + swz(n, koff));
            }
#pragma unroll
            for (int p = 0; p < 4; p++) {
                mma16816(acc[0][2 * p],     ah,     bb[4 * p + 0], bb[4 * p + 1]);
                mma16816(acc[1][2 * p],     ah + 4, bb[4 * p + 0], bb[4 * p + 1]);
                mma16816(acc[0][2 * p + 1], ah,     bb[4 * p + 2], bb[4 * p + 3]);
                mma16816(acc[1][2 * p + 1], ah + 4, bb[4 * p + 2], bb[4 * p + 3]);
            }
        }
        __syncthreads();
        int cn = c + NSTAGE;
        if (cn < NCHUNK) {
            size_t gk = (size_t)cn * BK * 2;
#pragma unroll
            for (int r = 0; r < 2; r++) {
                cp16(s0 + STG_A + swoff[r], pA + gbA[r] + gk);
                cp16(s0 + STG_B + swoff[r], pW + gbB[r] + gk);
            }
        }
        CP_COMMIT();
        slot = (slot + 1 == NSTAGE) ? 0 : slot + 1;
    }

    // Epilogue: tanh + V_w dot, reduce 8 partials per row
    const float* db = g_dbias + b * UU + uTile * BN + warp_n * 64;
    const float* vw = Vw + uTile * BN + warp_n * 64;
    float p[2][2] = {{0.f, 0.f}, {0.f, 0.f}};
#pragma unroll
    for (int mt = 0; mt < 2; mt++)
#pragma unroll
        for (int nt = 0; nt < 8; nt++) {
            int u0 = nt * 8 + (lane & 3) * 2;
            float d0 = db[u0], d1 = db[u0 + 1];
            float v0 = vw[u0], v1 = vw[u0 + 1];
            p[mt][0] += tanh_fast(acc[mt][nt][0] + d0) * v0
                      + tanh_fast(acc[mt][nt][1] + d1) * v1;
            p[mt][1] += tanh_fast(acc[mt][nt][2] + d0) * v0
                      + tanh_fast(acc[mt][nt][3] + d1) * v1;
        }
    float* red = (float*)(smem + SM_RED);
#pragma unroll
    for (int mt = 0; mt < 2; mt++)
#pragma unroll
        for (int half = 0; half < 2; half++) {
            int row = warp_m * 32 + mt * 16 + half * 8 + (lane >> 2);
            red[row * 8 + warp_n * 4 + (lane & 3)] = p[mt][half];
        }
    __syncthreads();
    if (tid < BM) {
        const float* rr = red + tid * 8;
        float s = 0.f;
#pragma unroll
        for (int j = 0; j < 8; j++) s += rr[j];
        atomicAdd(&out[OUT_SCORE + b * TT + tTile * BM + tid], s);
    }
}

// ---------------------------------------------------------------------------
// 3) Softmax over t per batch
// ---------------------------------------------------------------------------
__global__ void softmax_kernel(float* __restrict__ out) {
    int b = blockIdx.x;
    const float* sc = out + OUT_SCORE + b * TT;
    float* att = out + OUT_ATT + b * TT;
    __shared__ float sred[256];
    int tid = (int)threadIdx.x;
    float v[8];
    float m = -1e30f;
#pragma unroll
    for (int i = 0; i < 8; i++) {
        v[i] = sc[tid + 256 * i];
        m = fmaxf(m, v[i]);
    }
    sred[tid] = m;
    __syncthreads();
    for (int s = 128; s; s >>= 1) {
        if (tid < s) sred[tid] = fmaxf(sred[tid], sred[tid + s]);
        __syncthreads();
    }
    m = sred[0];
    __syncthreads();
    float sum = 0.f;
#pragma unroll
    for (int i = 0; i < 8; i++) {
        v[i] = expf(v[i] - m);
        sum += v[i];
    }
    sred[tid] = sum;
    __syncthreads();
    for (int s = 128; s; s >>= 1) {
        if (tid < s) sred[tid] += sred[tid + s];
        __syncthreads();
    }
    float inv = 1.f / sred[0];
#pragma unroll
    for (int i = 0; i < 8; i++) att[tid + 256 * i] = v[i] * inv;
}

// ---------------------------------------------------------------------------
// 4) context[b,h] = sum_t att[b,t] * Ah[b,t,h]  (fp16 values, half traffic)
// ---------------------------------------------------------------------------
__global__ void context_kernel(float* __restrict__ out) {
    int b = blockIdx.z;
    int h = blockIdx.x * 128 + (int)threadIdx.x;
    int t0 = blockIdx.y * 128;
    const float* att = out + OUT_ATT + b * TT;
    const __half* vp = g_Ah + ((size_t)b * TT + t0) * KP + h;
    float acc = 0.f;
#pragma unroll 8
    for (int t = 0; t < 128; t++) {
        acc = fmaf(att[t0 + t], __half2float(vp[(size_t)t * KP]), acc);
    }
    atomicAdd(&out[OUT_CTX + b * HH + h], acc);
}

// ---------------------------------------------------------------------------
extern "C" void kernel_launch(void* const* d_in, const int* in_sizes, int n_in,
                              void* d_out, int out_size) {
    const float* query   = (const float*)d_in[0];
    const float* values  = (const float*)d_in[1];
    const float* prev    = (const float*)d_in[2];
    const float* W1w     = (const float*)d_in[3];
    const float* W1b     = (const float*)d_in[4];
    const float* W2w     = (const float*)d_in[5];
    const float* W2b     = (const float*)d_in[6];
    const float* Vw      = (const float*)d_in[7];
    const float* Vb      = (const float*)d_in[8];
    const float* convw   = (const float*)d_in[9];
    const float* locpw   = (const float*)d_in[10];
    float* out = (float*)d_out;

    cudaFuncSetAttribute(score_gemm_tc,
                         cudaFuncAttributeMaxDynamicSharedMemorySize,
                         SMEM_GEMM_BYTES);

    prep_kernel<<<NB_PREP, 256>>>(values, prev, convw, query, W2w, W1b, W2b,
                                  W1w, locpw, Vb, out);
    score_gemm_tc<<<dim3(TT / BM, UU / BN, BB), 256, SMEM_GEMM_BYTES>>>(Vw, out);
    softmax_kernel<<<BB, 256>>>(out);
    context_kernel<<<dim3(HH / 128, TT / 128, BB), 128>>>(out);
}

// round 15
// speedup vs baseline: 1.0357x; 1.0357x over previous
#include <cuda_runtime.h>
#include <cuda_fp16.h>
#include <math.h>
#include <stdint.h>

// Problem constants
#define BB 32
#define TT 2048
#define HH 1024
#define UU 1024
#define KN 32
#define KSZ 15
#define KW 31
#define KAUG (HH + KN)   // 1056
#define KP 1056          // K (33 * 32 exactly)
#define BK 32            // K per chunk (fp16) = 64 bytes per row
#define NCHUNK (KP / BK) // 33
#define NSTAGE 6

#define BM 128
#define BN 128

// Output layout in d_out (float):
#define OUT_CTX 0
#define OUT_ATT (BB * HH)
#define OUT_SCORE (BB * HH + BB * TT)

// Scratch (device globals)
__device__ float g_dbias[BB * UU];
__device__ __half g_Ah[(size_t)BB * TT * KP];   // fp16(values | loc)
__device__ __half g_Wh[(size_t)UU * KP];        // fp16(W1_w | loc_proj_w)

// ---------------------------------------------------------------------------
__device__ __forceinline__ uint32_t smem_u32(const void* p) {
    uint32_t a;
    asm("{ .reg .u64 t; cvta.to.shared.u64 t, %1; cvt.u32.u64 %0, t; }"
        : "=r"(a) : "l"(p));
    return a;
}

__device__ __forceinline__ void cp16(uint32_t saddr, const void* gaddr) {
    asm volatile("cp.async.cg.shared.global [%0], [%1], 16;"
                 :: "r"(saddr), "l"(gaddr));
}
#define CP_COMMIT() asm volatile("cp.async.commit_group;" ::: "memory")
#define CP_WAIT5()  asm volatile("cp.async.wait_group 5;" ::: "memory")

__device__ __forceinline__ void ldm_x4(uint32_t* r, uint32_t addr) {
    asm volatile("ldmatrix.sync.aligned.m8n8.x4.shared.b16 {%0,%1,%2,%3}, [%4];"
                 : "=r"(r[0]), "=r"(r[1]), "=r"(r[2]), "=r"(r[3]) : "r"(addr));
}

__device__ __forceinline__ void mma16816(float* d, const uint32_t* a,
                                         uint32_t b0, uint32_t b1) {
    asm volatile(
        "mma.sync.aligned.m16n8k16.row.col.f32.f16.f16.f32 "
        "{%0,%1,%2,%3}, {%4,%5,%6,%7}, {%8,%9}, {%0,%1,%2,%3};"
        : "+f"(d[0]), "+f"(d[1]), "+f"(d[2]), "+f"(d[3])
        : "r"(a[0]), "r"(a[1]), "r"(a[2]), "r"(a[3]), "r"(b0), "r"(b1));
}

__device__ __forceinline__ float tanh_fast(float x) {
    float y;
    asm("tanh.approx.f32 %0, %1;" : "=f"(y) : "f"(x));
    return y;
}

// swizzle: 64B rows, XOR bits[5:4] with row bits[2:1] -> conflict-free ldmatrix
__device__ __forceinline__ uint32_t swz(int row, int inrow) {
    return (uint32_t)(row * 64 + (inrow ^ ((row & 6) << 3)));
}

// ---------------------------------------------------------------------------
// 1) Per-(b,u) bias
// ---------------------------------------------------------------------------
__global__ void dbias_kernel(const float* __restrict__ q,
                             const float* __restrict__ W2w,
                             const float* __restrict__ W1b,
                             const float* __restrict__ W2b) {
    int warp = threadIdx.x >> 5;
    int lane = threadIdx.x & 31;
    int u = blockIdx.x * 8 + warp;
    float w2[32];
#pragma unroll
    for (int i = 0; i < 32; i++) w2[i] = W2w[(size_t)u * HH + lane + 32 * i];
    float bias = W1b[u] + W2b[u];
    for (int b = 0; b < BB; b++) {
        float p = 0.f;
        const float* qb = q + (size_t)b * HH;
#pragma unroll
        for (int i = 0; i < 32; i++) p = fmaf(w2[i], qb[lane + 32 * i], p);
#pragma unroll
        for (int off = 16; off; off >>= 1) p += __shfl_xor_sync(0xFFFFFFFFu, p, off);
        if (lane == 0) g_dbias[b * UU + u] = p + bias;
    }
}

// ---------------------------------------------------------------------------
// 2) Fused conv + convert: row (b,t) -> g_Ah[row] = fp16(values[row] | loc)
// ---------------------------------------------------------------------------
__global__ void convertA_kernel(const float* __restrict__ values,
                                const float* __restrict__ prev,
                                const float* __restrict__ convw) {
    int row = (int)blockIdx.x;            // b * TT + t
    int b = row >> 11;                    // TT = 2048
    int t = row & (TT - 1);
    int tid = (int)threadIdx.x;
    __shared__ float loc[KN];

    if (tid < KN) {
        const float* pb = prev + b * TT;
        const float* w = convw + tid * KW;
        float acc = 0.f;
#pragma unroll
        for (int j = 0; j < KW; j++) {
            int tt = t + j - KSZ;
            float p = (tt >= 0 && tt < TT) ? pb[tt] : 0.f;
            acc = fmaf(p, w[j], acc);
        }
        loc[tid] = acc;
    }

    const float4* vrow = (const float4*)(values + (size_t)row * HH);
    __half* ah = g_Ah + (size_t)row * KP;
    {
        float4 v = vrow[tid];
        __half2* o = (__half2*)(ah + tid * 4);
        o[0] = __floats2half2_rn(v.x, v.y);
        o[1] = __floats2half2_rn(v.z, v.w);
    }
    __syncthreads();
    if (tid < 8) {
        const float4* lrow = (const float4*)loc;
        float4 v = lrow[tid];
        __half2* o = (__half2*)(ah + HH + tid * 4);
        o[0] = __floats2half2_rn(v.x, v.y);
        o[1] = __floats2half2_rn(v.z, v.w);
    }
}

// ---------------------------------------------------------------------------
// 3) [W1_w | loc_proj_w] -> fp16
// ---------------------------------------------------------------------------
__global__ void convertW_kernel(const float* __restrict__ W1w,
                                const float* __restrict__ locpw) {
    size_t u = blockIdx.x;
    const float* w1 = W1w + u * HH;
    const float* lp = locpw + u * KN;
    __half* wh = g_Wh + u * KP;
    for (int k = threadIdx.x; k < KP; k += blockDim.x) {
        float a = (k < HH) ? w1[k] : lp[k - HH];
        wh[k] = __float2half_rn(a);
    }
}

__global__ void init_out_kernel(const float* __restrict__ Vb, float* __restrict__ out) {
    int stride = gridDim.x * blockDim.x;
    int tid0 = blockIdx.x * blockDim.x + threadIdx.x;
    float vb = Vb[0];
    for (int i = tid0; i < BB * TT; i += stride) out[OUT_SCORE + i] = vb;
    for (int i = tid0; i < BB * HH; i += stride) out[OUT_CTX + i] = 0.f;
}

// ---------------------------------------------------------------------------
// 4) HMMA fp16 score GEMM, fused tanh + V_w epilogue
//    CTA 128x128, 8 warps (4m x 2n), BK=32, 6-stage cp.async (R8 loop order)
// ---------------------------------------------------------------------------
#define STG_A 0
#define STG_B 8192
#define STG_SZ 16384
#define SM_RED (NSTAGE * STG_SZ)                 // 98304
#define SMEM_GEMM_BYTES (NSTAGE * STG_SZ + BM * 8 * 4)   // 102400

__global__ void __launch_bounds__(256, 2)
score_gemm_tc(const float* __restrict__ Vw, float* __restrict__ out) {
    extern __shared__ char smem[];
    uint32_t sb = smem_u32(smem);

    int tid = (int)threadIdx.x;
    int lane = tid & 31;
    int wid = tid >> 5;
    int warp_m = wid >> 1;   // 0..3
    int warp_n = wid & 1;    // 0..1
    int b = blockIdx.z;
    int tTile = blockIdx.x;
    int uTile = blockIdx.y;

    size_t aRow0 = (size_t)b * TT + tTile * BM;
    size_t uRow0 = (size_t)uTile * BN;

    // per-thread load slots: 2 x 16B per array per chunk
    uint32_t swoff[2];
    size_t gbA[2], gbB[2];
#pragma unroll
    for (int r = 0; r < 2; r++) {
        int id = tid * 2 + r;
        int row = id >> 2;
        int sl = id & 3;
        swoff[r] = swz(row, sl * 16);
        gbA[r] = ((aRow0 + row) * KP + sl * 8) * 2;   // bytes
        gbB[r] = ((uRow0 + row) * KP + sl * 8) * 2;
    }

    const char* pA = (const char*)g_Ah;
    const char* pW = (const char*)g_Wh;

    // prologue: stages 0..5
#pragma unroll
    for (int c = 0; c < NSTAGE; c++) {
        uint32_t s0 = sb + c * STG_SZ;
        size_t gk = (size_t)c * BK * 2;
#pragma unroll
        for (int r = 0; r < 2; r++) {
            cp16(s0 + STG_A + swoff[r], pA + gbA[r] + gk);
            cp16(s0 + STG_B + swoff[r], pW + gbB[r] + gk);
        }
        CP_COMMIT();
    }

    float acc[2][8][4];
#pragma unroll
    for (int mt = 0; mt < 2; mt++)
#pragma unroll
        for (int nt = 0; nt < 8; nt++)
#pragma unroll
            for (int i = 0; i < 4; i++) acc[mt][nt][i] = 0.f;

    int slot = 0;
    for (int c = 0; c < NCHUNK; c++) {
        CP_WAIT5();
        __syncthreads();
        uint32_t s0 = sb + slot * STG_SZ;

#pragma unroll
        for (int ks = 0; ks < 2; ks++) {
            uint32_t ah[8];
#pragma unroll
            for (int mt = 0; mt < 2; mt++) {
                int row = warp_m * 32 + mt * 16 + (lane & 15);
                uint32_t off = swz(row, (ks * 2 + (lane >> 4)) * 16);
                ldm_x4(ah + mt * 4, s0 + STG_A + off);
            }
            uint32_t bb[16];
#pragma unroll
            for (int p = 0; p < 4; p++) {
                int t = lane >> 3;
                int n = warp_n * 64 + p * 16 + ((t & 2) ? 8 : 0) + (lane & 7);
                int koff = ks * 32 + ((t & 1) ? 16 : 0);
                ldm_x4(bb + p * 4, s0 + STG_B + swz(n, koff));
            }
#pragma unroll
            for (int p = 0; p < 4; p++) {
                mma16816(acc[0][2 * p],     ah,     bb[4 * p + 0], bb[4 * p + 1]);
                mma16816(acc[1][2 * p],     ah + 4, bb[4 * p + 0], bb[4 * p + 1]);
                mma16816(acc[0][2 * p + 1], ah,     bb[4 * p + 2], bb[4 * p + 3]);
                mma16816(acc[1][2 * p + 1], ah + 4, bb[4 * p + 2], bb[4 * p + 3]);
            }
        }
        __syncthreads();
        int cn = c + NSTAGE;
        if (cn < NCHUNK) {
            size_t gk = (size_t)cn * BK * 2;
#pragma unroll
            for (int r = 0; r < 2; r++) {
                cp16(s0 + STG_A + swoff[r], pA + gbA[r] + gk);
                cp16(s0 + STG_B + swoff[r], pW + gbB[r] + gk);
            }
        }
        CP_COMMIT();
        slot = (slot + 1 == NSTAGE) ? 0 : slot + 1;
    }

    // Epilogue: tanh + V_w dot, reduce 8 partials per row
    const float* db = g_dbias + b * UU + uTile * BN + warp_n * 64;
    const float* vw = Vw + uTile * BN + warp_n * 64;
    float p[2][2] = {{0.f, 0.f}, {0.f, 0.f}};
#pragma unroll
    for (int mt = 0; mt < 2; mt++)
#pragma unroll
        for (int nt = 0; nt < 8; nt++) {
            int u0 = nt * 8 + (lane & 3) * 2;
            float d0 = db[u0], d1 = db[u0 + 1];
            float v0 = vw[u0], v1 = vw[u0 + 1];
            p[mt][0] += tanh_fast(acc[mt][nt][0] + d0) * v0
                      + tanh_fast(acc[mt][nt][1] + d1) * v1;
            p[mt][1] += tanh_fast(acc[mt][nt][2] + d0) * v0
                      + tanh_fast(acc[mt][nt][3] + d1) * v1;
        }
    float* red = (float*)(smem + SM_RED);
#pragma unroll
    for (int mt = 0; mt < 2; mt++)
#pragma unroll
        for (int half = 0; half < 2; half++) {
            int row = warp_m * 32 + mt * 16 + half * 8 + (lane >> 2);
            red[row * 8 + warp_n * 4 + (lane & 3)] = p[mt][half];
        }
    __syncthreads();
    if (tid < BM) {
        const float* rr = red + tid * 8;
        float s = 0.f;
#pragma unroll
        for (int j = 0; j < 8; j++) s += rr[j];
        atomicAdd(&out[OUT_SCORE + b * TT + tTile * BM + tid], s);
    }
}

// ---------------------------------------------------------------------------
// 5) Softmax over t per batch
// ---------------------------------------------------------------------------
__global__ void softmax_kernel(float* __restrict__ out) {
    int b = blockIdx.x;
    const float* sc = out + OUT_SCORE + b * TT;
    float* att = out + OUT_ATT + b * TT;
    __shared__ float sred[256];
    int tid = (int)threadIdx.x;
    float v[8];
    float m = -1e30f;
#pragma unroll
    for (int i = 0; i < 8; i++) {
        v[i] = sc[tid + 256 * i];
        m = fmaxf(m, v[i]);
    }
    sred[tid] = m;
    __syncthreads();
    for (int s = 128; s; s >>= 1) {
        if (tid < s) sred[tid] = fmaxf(sred[tid], sred[tid + s]);
        __syncthreads();
    }
    m = sred[0];
    __syncthreads();
    float sum = 0.f;
#pragma unroll
    for (int i = 0; i < 8; i++) {
        v[i] = expf(v[i] - m);
        sum += v[i];
    }
    sred[tid] = sum;
    __syncthreads();
    for (int s = 128; s; s >>= 1) {
        if (tid < s) sred[tid] += sred[tid + s];
        __syncthreads();
    }
    float inv = 1.f / sred[0];
#pragma unroll
    for (int i = 0; i < 8; i++) att[tid + 256 * i] = v[i] * inv;
}

// ---------------------------------------------------------------------------
// 6) context[b,h] = sum_t att[b,t] * Ah[b,t,h]
//    half2 loads (2 h per thread) + 2 t-parity accumulators for MLP
// ---------------------------------------------------------------------------
__global__ void context_kernel(float* __restrict__ out) {
    int b = blockIdx.z;
    int h2 = blockIdx.x * 128 + (int)threadIdx.x;   // half2 index: h = 2*h2
    int t0 = blockIdx.y * 128;
    const float* att = out + OUT_ATT + b * TT + t0;
    const __half2* vp = (const __half2*)(g_Ah + ((size_t)b * TT + t0) * KP) + h2;
    float a00 = 0.f, a01 = 0.f, a10 = 0.f, a11 = 0.f;
#pragma unroll 8
    for (int t = 0; t < 128; t += 2) {
        float w0 = att[t];
        float w1 = att[t + 1];
        float2 v0 = __half22float2(vp[(size_t)t * (KP / 2)]);
        float2 v1 = __half22float2(vp[(size_t)(t + 1) * (KP / 2)]);
        a00 = fmaf(w0, v0.x, a00);
        a01 = fmaf(w0, v0.y, a01);
        a10 = fmaf(w1, v1.x, a10);
        a11 = fmaf(w1, v1.y, a11);
    }
    int h = h2 * 2;
    atomicAdd(&out[OUT_CTX + b * HH + h],     a00 + a10);
    atomicAdd(&out[OUT_CTX + b * HH + h + 1], a01 + a11);
}

// ---------------------------------------------------------------------------
extern "C" void kernel_launch(void* const* d_in, const int* in_sizes, int n_in,
                              void* d_out, int out_size) {
    const float* query   = (const float*)d_in[0];
    const float* values  = (const float*)d_in[1];
    const float* prev    = (const float*)d_in[2];
    const float* W1w     = (const float*)d_in[3];
    const float* W1b     = (const float*)d_in[4];
    const float* W2w     = (const float*)d_in[5];
    const float* W2b     = (const float*)d_in[6];
    const float* Vw      = (const float*)d_in[7];
    const float* Vb      = (const float*)d_in[8];
    const float* convw   = (const float*)d_in[9];
    const float* locpw   = (const float*)d_in[10];
    float* out = (float*)d_out;

    cudaFuncSetAttribute(score_gemm_tc,
                         cudaFuncAttributeMaxDynamicSharedMemorySize,
                         SMEM_GEMM_BYTES);

    dbias_kernel<<<UU / 8, 256>>>(query, W2w, W1b, W2b);
    convertA_kernel<<<BB * TT, 256>>>(values, prev, convw);
    convertW_kernel<<<UU, 256>>>(W1w, locpw);
    init_out_kernel<<<256, 256>>>(Vb, out);
    score_gemm_tc<<<dim3(TT / BM, UU / BN, BB), 256, SMEM_GEMM_BYTES>>>(Vw, out);
    softmax_kernel<<<BB, 256>>>(out);
    context_kernel<<<dim3(HH / 256, TT / 128, BB), 128>>>(out);
}

// round 16
// speedup vs baseline: 1.2123x; 1.1705x over previous
#include <cuda_runtime.h>
#include <cuda_fp16.h>
#include <math.h>
#include <stdint.h>

// Problem constants
#define BB 32
#define TT 2048
#define HH 1024
#define UU 1024
#define KN 32
#define KSZ 15
#define KW 31
#define KAUG (HH + KN)   // 1056
#define KP 1056          // K (33 * 32 exactly)
#define BK 32            // K per chunk (fp16) = 64 bytes per row
#define NCHUNK (KP / BK) // 33
#define NSTAGE 6

#define BM 128
#define BN 128

// Output layout in d_out (float):
#define OUT_CTX 0
#define OUT_ATT (BB * HH)
#define OUT_SCORE (BB * HH + BB * TT)

// prep kernel block-range dispatch: narrow/slow ranges FIRST, convertA mass last
#define NB_DB 512                       // dbias: 8 warps/block, warp = (u, 8 batches)
#define NB_W UU                         // 1024 convertW blocks
#define NB_INIT 256
#define NB_A (BB * TT)                  // 65536 convertA blocks
#define NB_PREP (NB_DB + NB_W + NB_INIT + NB_A)

// Scratch (device globals)
__device__ float g_dbias[BB * UU];
__device__ __half g_Ah[(size_t)BB * TT * KP];   // fp16(values | loc)
__device__ __half g_Wh[(size_t)UU * KP];        // fp16(W1_w | loc_proj_w)

// ---------------------------------------------------------------------------
__device__ __forceinline__ uint32_t smem_u32(const void* p) {
    uint32_t a;
    asm("{ .reg .u64 t; cvta.to.shared.u64 t, %1; cvt.u32.u64 %0, t; }"
        : "=r"(a) : "l"(p));
    return a;
}

__device__ __forceinline__ void cp16(uint32_t saddr, const void* gaddr) {
    asm volatile("cp.async.cg.shared.global [%0], [%1], 16;"
                 :: "r"(saddr), "l"(gaddr));
}
#define CP_COMMIT() asm volatile("cp.async.commit_group;" ::: "memory")
#define CP_WAIT5()  asm volatile("cp.async.wait_group 5;" ::: "memory")

__device__ __forceinline__ void ldm_x4(uint32_t* r, uint32_t addr) {
    asm volatile("ldmatrix.sync.aligned.m8n8.x4.shared.b16 {%0,%1,%2,%3}, [%4];"
                 : "=r"(r[0]), "=r"(r[1]), "=r"(r[2]), "=r"(r[3]) : "r"(addr));
}

__device__ __forceinline__ void mma16816(float* d, const uint32_t* a,
                                         uint32_t b0, uint32_t b1) {
    asm volatile(
        "mma.sync.aligned.m16n8k16.row.col.f32.f16.f16.f32 "
        "{%0,%1,%2,%3}, {%4,%5,%6,%7}, {%8,%9}, {%0,%1,%2,%3};"
        : "+f"(d[0]), "+f"(d[1]), "+f"(d[2]), "+f"(d[3])
        : "r"(a[0]), "r"(a[1]), "r"(a[2]), "r"(a[3]), "r"(b0), "r"(b1));
}

__device__ __forceinline__ float tanh_fast(float x) {
    float y;
    asm("tanh.approx.f32 %0, %1;" : "=f"(y) : "f"(x));
    return y;
}

// swizzle: 64B rows, XOR bits[5:4] with row bits[2:1] -> conflict-free ldmatrix
__device__ __forceinline__ uint32_t swz(int row, int inrow) {
    return (uint32_t)(row * 64 + (inrow ^ ((row & 6) << 3)));
}

// ---------------------------------------------------------------------------
// 1) Fused prep kernel. Ranges ordered: dbias | convertW | init | convertA.
// ---------------------------------------------------------------------------
__global__ void __launch_bounds__(256)
prep_kernel(const float* __restrict__ values,
            const float* __restrict__ prev,
            const float* __restrict__ convw,
            const float* __restrict__ q,
            const float* __restrict__ W2w,
            const float* __restrict__ W1b,
            const float* __restrict__ W2b,
            const float* __restrict__ W1w,
            const float* __restrict__ locpw,
            const float* __restrict__ Vb,
            float* __restrict__ out) {
    int bid = (int)blockIdx.x;
    int tid = (int)threadIdx.x;

    if (bid < NB_DB) {
        // ---- dbias: warp g handles u = g>>2, batches [ (g&3)*8, +8 ) ----
        int warp = tid >> 5;
        int lane = tid & 31;
        int g = bid * 8 + warp;
        int u = g >> 2;
        int b0 = (g & 3) * 8;
        float w2[32];
#pragma unroll
        for (int i = 0; i < 32; i++) w2[i] = W2w[(size_t)u * HH + lane + 32 * i];
        float bias = W1b[u] + W2b[u];
#pragma unroll
        for (int bb = 0; bb < 8; bb++) {
            int b = b0 + bb;
            float p = 0.f;
            const float* qb = q + (size_t)b * HH;
#pragma unroll
            for (int i = 0; i < 32; i++) p = fmaf(w2[i], qb[lane + 32 * i], p);
#pragma unroll
            for (int off = 16; off; off >>= 1) p += __shfl_xor_sync(0xFFFFFFFFu, p, off);
            if (lane == 0) g_dbias[b * UU + u] = p + bias;
        }
    } else if (bid < NB_DB + NB_W) {
        // ---- convertW: [W1_w | loc_proj_w] -> fp16 ----
        size_t u = bid - NB_DB;
        const float* w1 = W1w + u * HH;
        const float* lp = locpw + u * KN;
        __half* wh = g_Wh + u * KP;
        for (int k = tid; k < KP; k += 256) {
            float a = (k < HH) ? w1[k] : lp[k - HH];
            wh[k] = __float2half_rn(a);
        }
    } else if (bid < NB_DB + NB_W + NB_INIT) {
        // ---- init_out: score = V_b, context = 0 ----
        int bi = bid - (NB_DB + NB_W);
        int stride = NB_INIT * 256;
        int tid0 = bi * 256 + tid;
        float vb = Vb[0];
        for (int i = tid0; i < BB * TT; i += stride) out[OUT_SCORE + i] = vb;
        for (int i = tid0; i < BB * HH; i += stride) out[OUT_CTX + i] = 0.f;
    } else {
        // ---- convertA: row (b,t) -> g_Ah[row] = fp16(values[row] | loc) ----
        int row = bid - (NB_DB + NB_W + NB_INIT);
        int b = row >> 11;                // TT = 2048
        int t = row & (TT - 1);
        __shared__ float loc[KN];

        if (tid < KN) {
            const float* pb = prev + b * TT;
            const float* w = convw + tid * KW;
            float acc = 0.f;
#pragma unroll
            for (int j = 0; j < KW; j++) {
                int tt = t + j - KSZ;
                float p = (tt >= 0 && tt < TT) ? pb[tt] : 0.f;
                acc = fmaf(p, w[j], acc);
            }
            loc[tid] = acc;
        }

        const float4* vrow = (const float4*)(values + (size_t)row * HH);
        __half* ah = g_Ah + (size_t)row * KP;
        {
            float4 v = vrow[tid];
            __half2* o = (__half2*)(ah + tid * 4);
            o[0] = __floats2half2_rn(v.x, v.y);
            o[1] = __floats2half2_rn(v.z, v.w);
        }
        __syncthreads();
        if (tid < 8) {
            const float4* lrow = (const float4*)loc;
            float4 v = lrow[tid];
            __half2* o = (__half2*)(ah + HH + tid * 4);
            o[0] = __floats2half2_rn(v.x, v.y);
            o[1] = __floats2half2_rn(v.z, v.w);
        }
    }
}

// ---------------------------------------------------------------------------
// 2) HMMA fp16 score GEMM, fused tanh + V_w epilogue
//    CTA 128x128, 8 warps (4m x 2n), BK=32, 6-stage cp.async (R8 loop order)
// ---------------------------------------------------------------------------
#define STG_A 0
#define STG_B 8192
#define STG_SZ 16384
#define SM_RED (NSTAGE * STG_SZ)                 // 98304
#define SMEM_GEMM_BYTES (NSTAGE * STG_SZ + BM * 8 * 4)   // 102400

__global__ void __launch_bounds__(256, 2)
score_gemm_tc(const float* __restrict__ Vw, float* __restrict__ out) {
    extern __shared__ char smem[];
    uint32_t sb = smem_u32(smem);

    int tid = (int)threadIdx.x;
    int lane = tid & 31;
    int wid = tid >> 5;
    int warp_m = wid >> 1;   // 0..3
    int warp_n = wid & 1;    // 0..1
    int b = blockIdx.z;
    int tTile = blockIdx.x;
    int uTile = blockIdx.y;

    size_t aRow0 = (size_t)b * TT + tTile * BM;
    size_t uRow0 = (size_t)uTile * BN;

    // per-thread load slots: 2 x 16B per array per chunk
    uint32_t swoff[2];
    size_t gbA[2], gbB[2];
#pragma unroll
    for (int r = 0; r < 2; r++) {
        int id = tid * 2 + r;
        int row = id >> 2;
        int sl = id & 3;
        swoff[r] = swz(row, sl * 16);
        gbA[r] = ((aRow0 + row) * KP + sl * 8) * 2;   // bytes
        gbB[r] = ((uRow0 + row) * KP + sl * 8) * 2;
    }

    const char* pA = (const char*)g_Ah;
    const char* pW = (const char*)g_Wh;

    // prologue: stages 0..5
#pragma unroll
    for (int c = 0; c < NSTAGE; c++) {
        uint32_t s0 = sb + c * STG_SZ;
        size_t gk = (size_t)c * BK * 2;
#pragma unroll
        for (int r = 0; r < 2; r++) {
            cp16(s0 + STG_A + swoff[r], pA + gbA[r] + gk);
            cp16(s0 + STG_B + swoff[r], pW + gbB[r] + gk);
        }
        CP_COMMIT();
    }

    float acc[2][8][4];
#pragma unroll
    for (int mt = 0; mt < 2; mt++)
#pragma unroll
        for (int nt = 0; nt < 8; nt++)
#pragma unroll
            for (int i = 0; i < 4; i++) acc[mt][nt][i] = 0.f;

    int slot = 0;
    for (int c = 0; c < NCHUNK; c++) {
        CP_WAIT5();
        __syncthreads();
        uint32_t s0 = sb + slot * STG_SZ;

#pragma unroll
        for (int ks = 0; ks < 2; ks++) {
            uint32_t ah[8];
#pragma unroll
            for (int mt = 0; mt < 2; mt++) {
                int row = warp_m * 32 + mt * 16 + (lane & 15);
                uint32_t off = swz(row, (ks * 2 + (lane >> 4)) * 16);
                ldm_x4(ah + mt * 4, s0 + STG_A + off);
            }
            uint32_t bb[16];
#pragma unroll
            for (int p = 0; p < 4; p++) {
                int t = lane >> 3;
                int n = warp_n * 64 + p * 16 + ((t & 2) ? 8 : 0) + (lane & 7);
                int koff = ks * 32 + ((t & 1) ? 16 : 0);
                ldm_x4(bb + p * 4, s0 + STG_B + swz(n, koff));
            }
#pragma unroll
            for (int p = 0; p < 4; p++) {
                mma16816(acc[0][2 * p],     ah,     bb[4 * p + 0], bb[4 * p + 1]);
                mma16816(acc[1][2 * p],     ah + 4, bb[4 * p + 0], bb[4 * p + 1]);
                mma16816(acc[0][2 * p + 1], ah,     bb[4 * p + 2], bb[4 * p + 3]);
                mma16816(acc[1][2 * p + 1], ah + 4, bb[4 * p + 2], bb[4 * p + 3]);
            }
        }
        __syncthreads();
        int cn = c + NSTAGE;
        if (cn < NCHUNK) {
            size_t gk = (size_t)cn * BK * 2;
#pragma unroll
            for (int r = 0; r < 2; r++) {
                cp16(s0 + STG_A + swoff[r], pA + gbA[r] + gk);
                cp16(s0 + STG_B + swoff[r], pW + gbB[r] + gk);
            }
        }
        CP_COMMIT();
        slot = (slot + 1 == NSTAGE) ? 0 : slot + 1;
    }

    // Epilogue: tanh + V_w dot, reduce 8 partials per row
    const float* db = g_dbias + b * UU + uTile * BN + warp_n * 64;
    const float* vw = Vw + uTile * BN + warp_n * 64;
    float p[2][2] = {{0.f, 0.f}, {0.f, 0.f}};
#pragma unroll
    for (int mt = 0; mt < 2; mt++)
#pragma unroll
        for (int nt = 0; nt < 8; nt++) {
            int u0 = nt * 8 + (lane & 3) * 2;
            float d0 = db[u0], d1 = db[u0 + 1];
            float v0 = vw[u0], v1 = vw[u0 + 1];
            p[mt][0] += tanh_fast(acc[mt][nt][0] + d0) * v0
                      + tanh_fast(acc[mt][nt][1] + d1) * v1;
            p[mt][1] += tanh_fast(acc[mt][nt][2] + d0) * v0
                      + tanh_fast(acc[mt][nt][3] + d1) * v1;
        }
    float* red = (float*)(smem + SM_RED);
#pragma unroll
    for (int mt = 0; mt < 2; mt++)
#pragma unroll
        for (int half = 0; half < 2; half++) {
            int row = warp_m * 32 + mt * 16 + half * 8 + (lane >> 2);
            red[row * 8 + warp_n * 4 + (lane & 3)] = p[mt][half];
        }
    __syncthreads();
    if (tid < BM) {
        const float* rr = red + tid * 8;
        float s = 0.f;
#pragma unroll
        for (int j = 0; j < 8; j++) s += rr[j];
        atomicAdd(&out[OUT_SCORE + b * TT + tTile * BM + tid], s);
    }
}

// ---------------------------------------------------------------------------
// 3) Softmax over t per batch
// ---------------------------------------------------------------------------
__global__ void softmax_kernel(float* __restrict__ out) {
    int b = blockIdx.x;
    const float* sc = out + OUT_SCORE + b * TT;
    float* att = out + OUT_ATT + b * TT;
    __shared__ float sred[256];
    int tid = (int)threadIdx.x;
    float v[8];
    float m = -1e30f;
#pragma unroll
    for (int i = 0; i < 8; i++) {
        v[i] = sc[tid + 256 * i];
        m = fmaxf(m, v[i]);
    }
    sred[tid] = m;
    __syncthreads();
    for (int s = 128; s; s >>= 1) {
        if (tid < s) sred[tid] = fmaxf(sred[tid], sred[tid + s]);
        __syncthreads();
    }
    m = sred[0];
    __syncthreads();
    float sum = 0.f;
#pragma unroll
    for (int i = 0; i < 8; i++) {
        v[i] = expf(v[i] - m);
        sum += v[i];
    }
    sred[tid] = sum;
    __syncthreads();
    for (int s = 128; s; s >>= 1) {
        if (tid < s) sred[tid] += sred[tid + s];
        __syncthreads();
    }
    float inv = 1.f / sred[0];
#pragma unroll
    for (int i = 0; i < 8; i++) att[tid + 256 * i] = v[i] * inv;
}

// ---------------------------------------------------------------------------
// 4) context[b,h] = sum_t att[b,t] * Ah[b,t,h]
//    half2 loads (2 h per thread) + 2 t-parity accumulators for MLP
// ---------------------------------------------------------------------------
__global__ void context_kernel(float* __restrict__ out) {
    int b = blockIdx.z;
    int h2 = blockIdx.x * 128 + (int)threadIdx.x;   // half2 index: h = 2*h2
    int t0 = blockIdx.y * 128;
    const float* att = out + OUT_ATT + b * TT + t0;
    const __half2* vp = (const __half2*)(g_Ah + ((size_t)b * TT + t0) * KP) + h2;
    float a00 = 0.f, a01 = 0.f, a10 = 0.f, a11 = 0.f;
#pragma unroll 8
    for (int t = 0; t < 128; t += 2) {
        float w0 = att[t];
        float w1 = att[t + 1];
        float2 v0 = __half22float2(vp[(size_t)t * (KP / 2)]);
        float2 v1 = __half22float2(vp[(size_t)(t + 1) * (KP / 2)]);
        a00 = fmaf(w0, v0.x, a00);
        a01 = fmaf(w0, v0.y, a01);
        a10 = fmaf(w1, v1.x, a10);
        a11 = fmaf(w1, v1.y, a11);
    }
    int h = h2 * 2;
    atomicAdd(&out[OUT_CTX + b * HH + h],     a00 + a10);
    atomicAdd(&out[OUT_CTX + b * HH + h + 1], a01 + a11);
}

// ---------------------------------------------------------------------------
extern "C" void kernel_launch(void* const* d_in, const int* in_sizes, int n_in,
                              void* d_out, int out_size) {
    const float* query   = (const float*)d_in[0];
    const float* values  = (const float*)d_in[1];
    const float* prev    = (const float*)d_in[2];
    const float* W1w     = (const float*)d_in[3];
    const float* W1b     = (const float*)d_in[4];
    const float* W2w     = (const float*)d_in[5];
    const float* W2b     = (const float*)d_in[6];
    const float* Vw      = (const float*)d_in[7];
    const float* Vb      = (const float*)d_in[8];
    const float* convw   = (const float*)d_in[9];
    const float* locpw   = (const float*)d_in[10];
    float* out = (float*)d_out;

    cudaFuncSetAttribute(score_gemm_tc,
                         cudaFuncAttributeMaxDynamicSharedMemorySize,
                         SMEM_GEMM_BYTES);

    prep_kernel<<<NB_PREP, 256>>>(values, prev, convw, query, W2w, W1b, W2b,
                                  W1w, locpw, Vb, out);
    score_gemm_tc<<<dim3(TT / BM, UU / BN, BB), 256, SMEM_GEMM_BYTES>>>(Vw, out);
    softmax_kernel<<<BB, 256>>>(out);
    context_kernel<<<dim3(HH / 256, TT / 128, BB), 128>>>(out);
}

// round 17
// speedup vs baseline: 1.2226x; 1.0085x over previous
#include <cuda_runtime.h>
#include <cuda_fp16.h>
#include <math.h>
#include <stdint.h>

// Problem constants
#define BB 32
#define TT 2048
#define HH 1024
#define UU 1024
#define KN 32
#define KSZ 15
#define KW 31
#define KAUG (HH + KN)   // 1056
#define KP 1056          // K (33 * 32 exactly)
#define BK 32            // K per chunk (fp16) = 64 bytes per row
#define NCHUNK (KP / BK) // 33
#define NSTAGE 6

#define BM 128
#define BN 128

// Output layout in d_out (float):
#define OUT_CTX 0
#define OUT_ATT (BB * HH)
#define OUT_SCORE (BB * HH + BB * TT)

// prep kernel block-range dispatch: narrow/slow ranges FIRST, convertA mass last
#define NB_DB 512                       // dbias: 8 warps/block, warp = (u, 8 batches)
#define NB_W UU                         // 1024 convertW blocks
#define NB_INIT 256
#define NB_A (BB * TT)                  // 65536 convertA blocks
#define NB_PREP (NB_DB + NB_W + NB_INIT + NB_A)

// Scratch (device globals)
__device__ float g_dbias[BB * UU];
__device__ __half g_Ah[(size_t)BB * TT * KP];   // fp16(values | loc)
__device__ __half g_Wh[(size_t)UU * KP];        // fp16(W1_w | loc_proj_w)

// ---------------------------------------------------------------------------
__device__ __forceinline__ uint32_t smem_u32(const void* p) {
    uint32_t a;
    asm("{ .reg .u64 t; cvta.to.shared.u64 t, %1; cvt.u32.u64 %0, t; }"
        : "=r"(a) : "l"(p));
    return a;
}

__device__ __forceinline__ void cp16(uint32_t saddr, const void* gaddr) {
    asm volatile("cp.async.cg.shared.global [%0], [%1], 16;"
                 :: "r"(saddr), "l"(gaddr));
}
#define CP_COMMIT() asm volatile("cp.async.commit_group;" ::: "memory")
#define CP_WAIT5()  asm volatile("cp.async.wait_group 5;" ::: "memory")

__device__ __forceinline__ void ldm_x4(uint32_t* r, uint32_t addr) {
    asm volatile("ldmatrix.sync.aligned.m8n8.x4.shared.b16 {%0,%1,%2,%3}, [%4];"
                 : "=r"(r[0]), "=r"(r[1]), "=r"(r[2]), "=r"(r[3]) : "r"(addr));
}

__device__ __forceinline__ void mma16816(float* d, const uint32_t* a,
                                         uint32_t b0, uint32_t b1) {
    asm volatile(
        "mma.sync.aligned.m16n8k16.row.col.f32.f16.f16.f32 "
        "{%0,%1,%2,%3}, {%4,%5,%6,%7}, {%8,%9}, {%0,%1,%2,%3};"
        : "+f"(d[0]), "+f"(d[1]), "+f"(d[2]), "+f"(d[3])
        : "r"(a[0]), "r"(a[1]), "r"(a[2]), "r"(a[3]), "r"(b0), "r"(b1));
}

__device__ __forceinline__ float tanh_fast(float x) {
    float y;
    asm("tanh.approx.f32 %0, %1;" : "=f"(y) : "f"(x));
    return y;
}

// swizzle: 64B rows, XOR bits[5:4] with row bits[2:1] -> conflict-free ldmatrix
__device__ __forceinline__ uint32_t swz(int row, int inrow) {
    return (uint32_t)(row * 64 + (inrow ^ ((row & 6) << 3)));
}

// ---------------------------------------------------------------------------
// 1) Fused prep kernel. Ranges ordered: dbias | convertW | init | convertA.
// ---------------------------------------------------------------------------
__global__ void __launch_bounds__(256)
prep_kernel(const float* __restrict__ values,
            const float* __restrict__ prev,
            const float* __restrict__ convw,
            const float* __restrict__ q,
            const float* __restrict__ W2w,
            const float* __restrict__ W1b,
            const float* __restrict__ W2b,
            const float* __restrict__ W1w,
            const float* __restrict__ locpw,
            const float* __restrict__ Vb,
            float* __restrict__ out) {
    int bid = (int)blockIdx.x;
    int tid = (int)threadIdx.x;

    if (bid < NB_DB) {
        // ---- dbias: warp g handles u = g>>2, batches [ (g&3)*8, +8 ) ----
        int warp = tid >> 5;
        int lane = tid & 31;
        int g = bid * 8 + warp;
        int u = g >> 2;
        int b0 = (g & 3) * 8;
        float w2[32];
#pragma unroll
        for (int i = 0; i < 32; i++) w2[i] = W2w[(size_t)u * HH + lane + 32 * i];
        float bias = W1b[u] + W2b[u];
#pragma unroll
        for (int bb = 0; bb < 8; bb++) {
            int b = b0 + bb;
            float p = 0.f;
            const float* qb = q + (size_t)b * HH;
#pragma unroll
            for (int i = 0; i < 32; i++) p = fmaf(w2[i], qb[lane + 32 * i], p);
#pragma unroll
            for (int off = 16; off; off >>= 1) p += __shfl_xor_sync(0xFFFFFFFFu, p, off);
            if (lane == 0) g_dbias[b * UU + u] = p + bias;
        }
    } else if (bid < NB_DB + NB_W) {
        // ---- convertW: [W1_w | loc_proj_w] -> fp16 ----
        size_t u = bid - NB_DB;
        const float* w1 = W1w + u * HH;
        const float* lp = locpw + u * KN;
        __half* wh = g_Wh + u * KP;
        for (int k = tid; k < KP; k += 256) {
            float a = (k < HH) ? w1[k] : lp[k - HH];
            wh[k] = __float2half_rn(a);
        }
    } else if (bid < NB_DB + NB_W + NB_INIT) {
        // ---- init_out: score = V_b, context = 0 ----
        int bi = bid - (NB_DB + NB_W);
        int stride = NB_INIT * 256;
        int tid0 = bi * 256 + tid;
        float vb = Vb[0];
        for (int i = tid0; i < BB * TT; i += stride) out[OUT_SCORE + i] = vb;
        for (int i = tid0; i < BB * HH; i += stride) out[OUT_CTX + i] = 0.f;
    } else {
        // ---- convertA: row (b,t) -> g_Ah[row] = fp16(values[row] | loc) ----
        int row = bid - (NB_DB + NB_W + NB_INIT);
        int b = row >> 11;                // TT = 2048
        int t = row & (TT - 1);
        __shared__ float loc[KN];

        if (tid < KN) {
            const float* pb = prev + b * TT;
            const float* w = convw + tid * KW;
            float acc = 0.f;
#pragma unroll
            for (int j = 0; j < KW; j++) {
                int tt = t + j - KSZ;
                float p = (tt >= 0 && tt < TT) ? pb[tt] : 0.f;
                acc = fmaf(p, w[j], acc);
            }
            loc[tid] = acc;
        }

        const float4* vrow = (const float4*)(values + (size_t)row * HH);
        __half* ah = g_Ah + (size_t)row * KP;
        {
            float4 v = vrow[tid];
            __half2* o = (__half2*)(ah + tid * 4);
            o[0] = __floats2half2_rn(v.x, v.y);
            o[1] = __floats2half2_rn(v.z, v.w);
        }
        __syncthreads();
        if (tid < 8) {
            const float4* lrow = (const float4*)loc;
            float4 v = lrow[tid];
            __half2* o = (__half2*)(ah + HH + tid * 4);
            o[0] = __floats2half2_rn(v.x, v.y);
            o[1] = __floats2half2_rn(v.z, v.w);
        }
    }
}

// ---------------------------------------------------------------------------
// 2) HMMA fp16 score GEMM, fused tanh + V_w epilogue
//    CTA 128x128, 8 warps (4m x 2n), BK=32, 6-stage cp.async (R8 loop order)
// ---------------------------------------------------------------------------
#define STG_A 0
#define STG_B 8192
#define STG_SZ 16384
#define SM_RED (NSTAGE * STG_SZ)                 // 98304
#define SMEM_GEMM_BYTES (NSTAGE * STG_SZ + BM * 8 * 4)   // 102400

__global__ void __launch_bounds__(256, 2)
score_gemm_tc(const float* __restrict__ Vw, float* __restrict__ out) {
    extern __shared__ char smem[];
    uint32_t sb = smem_u32(smem);

    int tid = (int)threadIdx.x;
    int lane = tid & 31;
    int wid = tid >> 5;
    int warp_m = wid >> 1;   // 0..3
    int warp_n = wid & 1;    // 0..1
    int b = blockIdx.z;
    int tTile = blockIdx.x;
    int uTile = blockIdx.y;

    size_t aRow0 = (size_t)b * TT + tTile * BM;
    size_t uRow0 = (size_t)uTile * BN;

    // per-thread load slots: 2 x 16B per array per chunk
    uint32_t swoff[2];
    size_t gbA[2], gbB[2];
#pragma unroll
    for (int r = 0; r < 2; r++) {
        int id = tid * 2 + r;
        int row = id >> 2;
        int sl = id & 3;
        swoff[r] = swz(row, sl * 16);
        gbA[r] = ((aRow0 + row) * KP + sl * 8) * 2;   // bytes
        gbB[r] = ((uRow0 + row) * KP + sl * 8) * 2;
    }

    const char* pA = (const char*)g_Ah;
    const char* pW = (const char*)g_Wh;

    // prologue: stages 0..5
#pragma unroll
    for (int c = 0; c < NSTAGE; c++) {
        uint32_t s0 = sb + c * STG_SZ;
        size_t gk = (size_t)c * BK * 2;
#pragma unroll
        for (int r = 0; r < 2; r++) {
            cp16(s0 + STG_A + swoff[r], pA + gbA[r] + gk);
            cp16(s0 + STG_B + swoff[r], pW + gbB[r] + gk);
        }
        CP_COMMIT();
    }

    float acc[2][8][4];
#pragma unroll
    for (int mt = 0; mt < 2; mt++)
#pragma unroll
        for (int nt = 0; nt < 8; nt++)
#pragma unroll
            for (int i = 0; i < 4; i++) acc[mt][nt][i] = 0.f;

    int slot = 0;
    for (int c = 0; c < NCHUNK; c++) {
        CP_WAIT5();
        __syncthreads();
        uint32_t s0 = sb + slot * STG_SZ;

#pragma unroll
        for (int ks = 0; ks < 2; ks++) {
            uint32_t ah[8];
#pragma unroll
            for (int mt = 0; mt < 2; mt++) {
                int row = warp_m * 32 + mt * 16 + (lane & 15);
                uint32_t off = swz(row, (ks * 2 + (lane >> 4)) * 16);
                ldm_x4(ah + mt * 4, s0 + STG_A + off);
            }
            uint32_t bb[16];
#pragma unroll
            for (int p = 0; p < 4; p++) {
                int t = lane >> 3;
                int n = warp_n * 64 + p * 16 + ((t & 2) ? 8 : 0) + (lane & 7);
                int koff = ks * 32 + ((t & 1) ? 16 : 0);
                ldm_x4(bb + p * 4, s0 + STG_B + swz(n, koff));
            }
#pragma unroll
            for (int p = 0; p < 4; p++) {
                mma16816(acc[0][2 * p],     ah,     bb[4 * p + 0], bb[4 * p + 1]);
                mma16816(acc[1][2 * p],     ah + 4, bb[4 * p + 0], bb[4 * p + 1]);
                mma16816(acc[0][2 * p + 1], ah,     bb[4 * p + 2], bb[4 * p + 3]);
                mma16816(acc[1][2 * p + 1], ah + 4, bb[4 * p + 2], bb[4 * p + 3]);
            }
        }
        __syncthreads();
        int cn = c + NSTAGE;
        if (cn < NCHUNK) {
            size_t gk = (size_t)cn * BK * 2;
#pragma unroll
            for (int r = 0; r < 2; r++) {
                cp16(s0 + STG_A + swoff[r], pA + gbA[r] + gk);
                cp16(s0 + STG_B + swoff[r], pW + gbB[r] + gk);
            }
        }
        CP_COMMIT();
        slot = (slot + 1 == NSTAGE) ? 0 : slot + 1;
    }

    // Epilogue: tanh + V_w dot, reduce 8 partials per row
    const float* db = g_dbias + b * UU + uTile * BN + warp_n * 64;
    const float* vw = Vw + uTile * BN + warp_n * 64;
    float p[2][2] = {{0.f, 0.f}, {0.f, 0.f}};
#pragma unroll
    for (int mt = 0; mt < 2; mt++)
#pragma unroll
        for (int nt = 0; nt < 8; nt++) {
            int u0 = nt * 8 + (lane & 3) * 2;
            float d0 = db[u0], d1 = db[u0 + 1];
            float v0 = vw[u0], v1 = vw[u0 + 1];
            p[mt][0] += tanh_fast(acc[mt][nt][0] + d0) * v0
                      + tanh_fast(acc[mt][nt][1] + d1) * v1;
            p[mt][1] += tanh_fast(acc[mt][nt][2] + d0) * v0
                      + tanh_fast(acc[mt][nt][3] + d1) * v1;
        }
    float* red = (float*)(smem + SM_RED);
#pragma unroll
    for (int mt = 0; mt < 2; mt++)
#pragma unroll
        for (int half = 0; half < 2; half++) {
            int row = warp_m * 32 + mt * 16 + half * 8 + (lane >> 2);
            red[row * 8 + warp_n * 4 + (lane & 3)] = p[mt][half];
        }
    __syncthreads();
    if (tid < BM) {
        const float* rr = red + tid * 8;
        float s = 0.f;
#pragma unroll
        for (int j = 0; j < 8; j++) s += rr[j];
        atomicAdd(&out[OUT_SCORE + b * TT + tTile * BM + tid], s);
    }
}

// ---------------------------------------------------------------------------
// 3) Fused softmax + context. Each block recomputes the per-batch softmax
//    reduction (8KB score read from L2), then does its context t-slice.
//    grid (HH/256, TT/128, BB), block 128. hx==0 blocks write att output.
// ---------------------------------------------------------------------------
__global__ void __launch_bounds__(128)
softmax_context_kernel(float* __restrict__ out) {
    int b = blockIdx.z;
    int hx = blockIdx.x;                  // 0..3 (h2 range)
    int t0 = blockIdx.y * 128;
    int tid = (int)threadIdx.x;

    const float* sc = out + OUT_SCORE + b * TT;
    __shared__ float sred[128];
    __shared__ float att_s[128];

    // softmax reduction over all TT scores (16 per thread)
    float v[16];
    float m = -1e30f;
#pragma unroll
    for (int i = 0; i < 16; i++) {
        v[i] = sc[tid + 128 * i];
        m = fmaxf(m, v[i]);
    }
    sred[tid] = m;
    __syncthreads();
    for (int s = 64; s; s >>= 1) {
        if (tid < s) sred[tid] = fmaxf(sred[tid], sred[tid + s]);
        __syncthreads();
    }
    m = sred[0];
    __syncthreads();
    float sum = 0.f;
#pragma unroll
    for (int i = 0; i < 16; i++) sum += expf(v[i] - m);
    sred[tid] = sum;
    __syncthreads();
    for (int s = 64; s; s >>= 1) {
        if (tid < s) sred[tid] += sred[tid + s];
        __syncthreads();
    }
    float inv = 1.f / sred[0];

    // att for this block's t-slice (one t per thread)
    float a = expf(sc[t0 + tid] - m) * inv;
    att_s[tid] = a;
    if (hx == 0) out[OUT_ATT + b * TT + t0 + tid] = a;
    __syncthreads();

    // context over t in [t0, t0+128), h2 = hx*128 + tid (2 h per thread)
    int h2 = hx * 128 + tid;
    const __half2* vp = (const __half2*)(g_Ah + ((size_t)b * TT + t0) * KP) + h2;
    float a0 = 0.f, a1 = 0.f, a2 = 0.f, a3 = 0.f;
    float b0 = 0.f, b1 = 0.f, b2 = 0.f, b3 = 0.f;
#pragma unroll 4
    for (int t = 0; t < 128; t += 4) {
        float w0 = att_s[t];
        float w1 = att_s[t + 1];
        float w2 = att_s[t + 2];
        float w3 = att_s[t + 3];
        float2 v0 = __half22float2(vp[(size_t)(t + 0) * (KP / 2)]);
        float2 v1 = __half22float2(vp[(size_t)(t + 1) * (KP / 2)]);
        float2 v2 = __half22float2(vp[(size_t)(t + 2) * (KP / 2)]);
        float2 v3 = __half22float2(vp[(size_t)(t + 3) * (KP / 2)]);
        a0 = fmaf(w0, v0.x, a0); b0 = fmaf(w0, v0.y, b0);
        a1 = fmaf(w1, v1.x, a1); b1 = fmaf(w1, v1.y, b1);
        a2 = fmaf(w2, v2.x, a2); b2 = fmaf(w2, v2.y, b2);
        a3 = fmaf(w3, v3.x, a3); b3 = fmaf(w3, v3.y, b3);
    }
    int h = h2 * 2;
    atomicAdd(&out[OUT_CTX + b * HH + h],     (a0 + a1) + (a2 + a3));
    atomicAdd(&out[OUT_CTX + b * HH + h + 1], (b0 + b1) + (b2 + b3));
}

// ---------------------------------------------------------------------------
extern "C" void kernel_launch(void* const* d_in, const int* in_sizes, int n_in,
                              void* d_out, int out_size) {
    const float* query   = (const float*)d_in[0];
    const float* values  = (const float*)d_in[1];
    const float* prev    = (const float*)d_in[2];
    const float* W1w     = (const float*)d_in[3];
    const float* W1b     = (const float*)d_in[4];
    const float* W2w     = (const float*)d_in[5];
    const float* W2b     = (const float*)d_in[6];
    const float* Vw      = (const float*)d_in[7];
    const float* Vb      = (const float*)d_in[8];
    const float* convw   = (const float*)d_in[9];
    const float* locpw   = (const float*)d_in[10];
    float* out = (float*)d_out;

    cudaFuncSetAttribute(score_gemm_tc,
                         cudaFuncAttributeMaxDynamicSharedMemorySize,
                         SMEM_GEMM_BYTES);

    prep_kernel<<<NB_PREP, 256>>>(values, prev, convw, query, W2w, W1b, W2b,
                                  W1w, locpw, Vb, out);
    score_gemm_tc<<<dim3(TT / BM, UU / BN, BB), 256, SMEM_GEMM_BYTES>>>(Vw, out);
    softmax_context_kernel<<<dim3(HH / 256, TT / 128, BB), 128>>>(out);
}